// round 1
// baseline (speedup 1.0000x reference)
#include <cuda_runtime.h>
#include <math.h>

#define KC 8192   // codebook size
#define DD 128    // embed dim
#define NR 8192   // number of z rows (8*32*32)
#define TM 64     // z rows per block
#define TN 64     // codes per k-tile

// Scratch (no allocations allowed)
__device__ float g_qc[KC * DD];
__device__ float g_cnorm[KC];
__device__ float g_counts[KC];
__device__ float g_commit;

// ---------------------------------------------------------------------------
// Kernel 1: qc = emb @ proj_w^T + proj_b ; cnorm[k] = ||qc_k||^2 ; zero counts
// One block per code row; thread t computes output dim t.
// ---------------------------------------------------------------------------
__global__ __launch_bounds__(128) void k_proj(const float* __restrict__ emb,
                                              const float* __restrict__ pw,
                                              const float* __restrict__ pb) {
    int code = blockIdx.x;
    int t = threadIdx.x;
    __shared__ float4 e_s[32];
    __shared__ float red[4];
    if (t < 32) e_s[t] = ((const float4*)(emb + (size_t)code * DD))[t];
    __syncthreads();
    const float4* pr = (const float4*)(pw + (size_t)t * DD);
    float acc = 0.f;
#pragma unroll
    for (int i = 0; i < 32; i++) {
        float4 p = pr[i];
        float4 e = e_s[i];
        acc += e.x * p.x; acc += e.y * p.y; acc += e.z * p.z; acc += e.w * p.w;
    }
    acc += pb[t];
    g_qc[(size_t)code * DD + t] = acc;

    float sq = acc * acc;
#pragma unroll
    for (int o = 16; o; o >>= 1) sq += __shfl_xor_sync(0xffffffffu, sq, o);
    if ((t & 31) == 0) red[t >> 5] = sq;
    __syncthreads();
    if (t == 0) {
        g_cnorm[code] = (red[0] + red[1]) + (red[2] + red[3]);
        g_counts[code] = 0.f;
        if (code == 0) g_commit = 0.f;
    }
}

// ---------------------------------------------------------------------------
// Kernel 2: fused distance-GEMM + argmin + gather + counts + commit partial
// Block: 256 threads, TM=64 z-rows, loop K in TN=64 tiles, 4x4 micro-tile.
// smem (dynamic): zs[128][64] d-major, cs[128][64] d-major, znorm[64], bestkey[64]
// ---------------------------------------------------------------------------
extern __shared__ float smem_dyn[];

__global__ __launch_bounds__(256) void k_argmin(const float* __restrict__ z,
                                                float* __restrict__ out) {
    float* zs = smem_dyn;                 // [DD][TM]
    float* cs = smem_dyn + DD * TM;       // [DD][TN]
    float* znorm_s = cs + DD * TN;        // [TM]
    unsigned long long* bestkey =
        (unsigned long long*)(znorm_s + TM);  // [TM], 8B-aligned (offset 65792)

    const int tid = threadIdx.x;
    const int n0 = blockIdx.x * TM;
    const int tc = tid & 15;   // 0..15 -> 4 codes each
    const int rg = tid >> 4;   // 0..15 -> 4 rows each
    const int c_ld = tid & 63; // loader row/code index
    const int dq4 = tid >> 6;  // loader d-quadrant 0..3

    // Load z tile transposed (d-major) into smem
    {
        const float4* zr = (const float4*)(z + (size_t)(n0 + c_ld) * DD) + dq4 * 8;
#pragma unroll
        for (int i = 0; i < 8; i++) {
            float4 v = zr[i];
            int d = (dq4 * 8 + i) * 4;
            zs[(d + 0) * TM + c_ld] = v.x;
            zs[(d + 1) * TM + c_ld] = v.y;
            zs[(d + 2) * TM + c_ld] = v.z;
            zs[(d + 3) * TM + c_ld] = v.w;
        }
    }
    if (tid >= 256 - TM) bestkey[tid - (256 - TM)] = ~0ULL;
    __syncthreads();

    // Row norms (||z_n||^2), fp32 sequential over d like the reference
    if (tid < TM) {
        float s = 0.f;
#pragma unroll 16
        for (int d = 0; d < DD; d++) { float v = zs[d * TM + tid]; s += v * v; }
        znorm_s[tid] = s;
    }
    __syncthreads();

    float zn[4];
#pragma unroll
    for (int i = 0; i < 4; i++) zn[i] = znorm_s[rg * 4 + i];

    float bestv[4] = {3.4e38f, 3.4e38f, 3.4e38f, 3.4e38f};
    int bestidx[4] = {0, 0, 0, 0};

    const float4* qc4 = (const float4*)g_qc;

    for (int kt = 0; kt < KC; kt += TN) {
        // Prefetch next code tile into registers (overlaps tail of prev compute)
        float4 pf[8];
        const float4* src = qc4 + (size_t)(kt + c_ld) * (DD / 4) + dq4 * 8;
#pragma unroll
        for (int i = 0; i < 8; i++) pf[i] = src[i];

        __syncthreads();  // prior tile's cs fully consumed
#pragma unroll
        for (int i = 0; i < 8; i++) {
            int d = (dq4 * 8 + i) * 4;
            cs[(d + 0) * TN + c_ld] = pf[i].x;
            cs[(d + 1) * TN + c_ld] = pf[i].y;
            cs[(d + 2) * TN + c_ld] = pf[i].z;
            cs[(d + 3) * TN + c_ld] = pf[i].w;
        }
        __syncthreads();

        float acc[4][4];
#pragma unroll
        for (int i = 0; i < 4; i++)
#pragma unroll
            for (int j = 0; j < 4; j++) acc[i][j] = 0.f;

        const float* zp = zs + rg * 4;
        const float* cp = cs + tc * 4;
#pragma unroll 16
        for (int d = 0; d < DD; d++) {
            float4 a = *(const float4*)(zp + d * TM);
            float4 b = *(const float4*)(cp + d * TN);
            acc[0][0] += a.x * b.x; acc[0][1] += a.x * b.y; acc[0][2] += a.x * b.z; acc[0][3] += a.x * b.w;
            acc[1][0] += a.y * b.x; acc[1][1] += a.y * b.y; acc[1][2] += a.y * b.z; acc[1][3] += a.y * b.w;
            acc[2][0] += a.z * b.x; acc[2][1] += a.z * b.y; acc[2][2] += a.z * b.z; acc[2][3] += a.z * b.w;
            acc[3][0] += a.w * b.x; acc[3][1] += a.w * b.y; acc[3][2] += a.w * b.z; acc[3][3] += a.w * b.w;
        }

        // Epilogue: d = (||z||^2 + ||c||^2) - 2*dot, same fp32 structure as ref
        int kb = kt + tc * 4;
#pragma unroll
        for (int j = 0; j < 4; j++) {
            float cn = __ldg(&g_cnorm[kb + j]);
#pragma unroll
            for (int i = 0; i < 4; i++) {
                float sc = (zn[i] + cn) - 2.0f * acc[i][j];
                if (sc < bestv[i]) { bestv[i] = sc; bestidx[i] = kb + j; }
            }
        }
    }

    // Merge per-thread bests across the 16 column-threads of each row.
    // Key = order-preserving float bits in high 32, index in low 32:
    // atomicMin picks smallest distance, then smallest index (matches argmin).
#pragma unroll
    for (int i = 0; i < 4; i++) {
        unsigned ub = __float_as_uint(bestv[i]);
        ub = (ub & 0x80000000u) ? ~ub : (ub | 0x80000000u);
        unsigned long long key = ((unsigned long long)ub << 32) | (unsigned)bestidx[i];
        atomicMin(&bestkey[rg * 4 + i], key);
    }
    __syncthreads();

    // Usage counts (one thread per row)
    if (tid < TM) {
        unsigned idxk = (unsigned)(bestkey[tid] & 0xffffffffu);
        atomicAdd(&g_counts[idxk], 1.0f);
    }

    // Gather z_q = z + (qc[idx] - z) (matches straight-through fp ops),
    // accumulate commit partial sum.
    float csum = 0.f;
    {
        int r = tid >> 2, part = tid & 3;
        unsigned idxk = (unsigned)(bestkey[r] & 0xffffffffu);
        const float4* qv = (const float4*)(g_qc + (size_t)idxk * DD) + part * 8;
        const float4* zv = (const float4*)(z + (size_t)(n0 + r) * DD) + part * 8;
        float4* ov = (float4*)(out + (size_t)(n0 + r) * DD) + part * 8;
#pragma unroll
        for (int i = 0; i < 8; i++) {
            float4 q = qv[i], zz = zv[i], o;
            float dx = q.x - zz.x, dy = q.y - zz.y, dz2 = q.z - zz.z, dw = q.w - zz.w;
            o.x = zz.x + dx; o.y = zz.y + dy; o.z = zz.z + dz2; o.w = zz.w + dw;
            ov[i] = o;
            csum += dx * dx; csum += dy * dy; csum += dz2 * dz2; csum += dw * dw;
        }
    }
#pragma unroll
    for (int o = 16; o; o >>= 1) csum += __shfl_xor_sync(0xffffffffu, csum, o);
    __shared__ float credu[8];
    if ((tid & 31) == 0) credu[tid >> 5] = csum;
    __syncthreads();
    if (tid == 0) {
        float t = 0.f;
#pragma unroll
        for (int i = 0; i < 8; i++) t += credu[i];
        atomicAdd(&g_commit, t);
    }
}

// ---------------------------------------------------------------------------
// Kernel 3: finalize scalars: commit_loss, perplexity, ema_entropy
// ---------------------------------------------------------------------------
__global__ __launch_bounds__(256) void k_final(const float* __restrict__ ema,
                                               float* __restrict__ out,
                                               int out_size) {
    __shared__ float r1[8], r2[8];
    int tid = threadIdx.x;
    const float omd = 1.0f - 0.99f;  // match reference's (1 - EMA_DECAY) in fp32
    float s1 = 0.f, s2 = 0.f;
    for (int k = tid; k < KC; k += 256) {
        float em = g_counts[k] * (1.0f / NR);  // exact: /8192
        s1 += em * logf(em + 1e-10f);
        float nu = ema[k] * 0.99f + em * omd;
        s2 += nu * logf(nu + 1e-10f);
    }
#pragma unroll
    for (int o = 16; o; o >>= 1) {
        s1 += __shfl_xor_sync(0xffffffffu, s1, o);
        s2 += __shfl_xor_sync(0xffffffffu, s2, o);
    }
    if ((tid & 31) == 0) { r1[tid >> 5] = s1; r2[tid >> 5] = s2; }
    __syncthreads();
    if (tid == 0) {
        float S1 = 0.f, S2 = 0.f;
#pragma unroll
        for (int i = 0; i < 8; i++) { S1 += r1[i]; S2 += r2[i]; }
        // commit = BETA*mean + mean = 1.25 * mean((zq-z)^2); /1048576 exact
        out[out_size - 3] = 1.25f * g_commit * (1.0f / ((float)NR * (float)DD));
        out[out_size - 2] = expf(-S1);
        out[out_size - 1] = -S2;
    }
}

// ---------------------------------------------------------------------------
extern "C" void kernel_launch(void* const* d_in, const int* in_sizes, int n_in,
                              void* d_out, int out_size) {
    const float* z   = (const float*)d_in[0];  // [8192,128]
    const float* emb = (const float*)d_in[1];  // [8192,128]
    const float* pw  = (const float*)d_in[2];  // [128,128]
    const float* pb  = (const float*)d_in[3];  // [128]
    const float* ema = (const float*)d_in[4];  // [8192]
    float* out = (float*)d_out;

    const int smem_bytes = (DD * TM + DD * TN + TM) * 4 + TM * 8;  // 66304
    cudaFuncSetAttribute(k_argmin, cudaFuncAttributeMaxDynamicSharedMemorySize,
                         smem_bytes);

    k_proj<<<KC, 128>>>(emb, pw, pb);
    k_argmin<<<NR / TM, 256, smem_bytes>>>(z, out);
    k_final<<<1, 256>>>(ema, out, out_size);
}

// round 2
// speedup vs baseline: 1.5541x; 1.5541x over previous
#include <cuda_runtime.h>
#include <math.h>

#define KC 8192   // codebook size
#define DD 128    // embed dim
#define NR 8192   // number of z rows
#define TM 64     // z rows per argmin block
#define TN 256    // codes per k-tile

typedef unsigned long long ull;

__device__ float g_qc[KC * DD];
__device__ float g_cnorm[KC];
__device__ float g_counts[KC];
__device__ float g_commit;

// ---- packed f32x2 helpers (Blackwell FFMA2 path) ----
__device__ __forceinline__ ull ffma2(ull a, ull b, ull c) {
    ull d;
    asm("fma.rn.f32x2 %0, %1, %2, %3;" : "=l"(d) : "l"(a), "l"(b), "l"(c));
    return d;
}
__device__ __forceinline__ ull pack2(float x) {
    ull r;
    asm("mov.b64 %0, {%1, %1};" : "=l"(r) : "f"(x));
    return r;
}
__device__ __forceinline__ float2 unpack2(ull v) {
    float2 r;
    asm("mov.b64 {%0, %1}, %2;" : "=f"(r.x), "=f"(r.y) : "l"(v));
    return r;
}

// ---------------------------------------------------------------------------
// Kernel 1: tiled GEMM qc = emb @ pw^T + pb ; cnorm ; init counts/commit.
// 64 blocks x 128 codes, 256 threads, 8x8 scalar micro-tile.
// dyn smem: pwT[128k][128n] (64KB) + ebT[128k][128c] (64KB) + cn_s[128]
// ---------------------------------------------------------------------------
extern __shared__ float smem_dyn[];

__global__ __launch_bounds__(256) void k_proj(const float* __restrict__ emb,
                                              const float* __restrict__ pw,
                                              const float* __restrict__ pb) {
    float* pwT = smem_dyn;            // [k*128 + n]
    float* ebT = smem_dyn + 16384;    // [k*128 + c]
    float* cn_s = ebT + 16384;        // [128]

    const int tid = threadIdx.x;
    const int c0 = blockIdx.x * 128;

    int gid = blockIdx.x * 256 + tid;
    if (gid < KC) g_counts[gid] = 0.f;
    if (gid == 0) g_commit = 0.f;
    if (tid < 128) cn_s[tid] = 0.f;

    // load pw transposed: pwT[k][n] = pw[n][k]
    {
        int n = tid & 127, h = tid >> 7;
        const float4* pr = (const float4*)(pw + (size_t)n * DD) + h * 16;
#pragma unroll
        for (int i = 0; i < 16; i++) {
            float4 v = pr[i];
            int k = (h * 16 + i) * 4;
            pwT[(k + 0) * 128 + n] = v.x; pwT[(k + 1) * 128 + n] = v.y;
            pwT[(k + 2) * 128 + n] = v.z; pwT[(k + 3) * 128 + n] = v.w;
        }
    }
    // load emb rows transposed: ebT[k][c]
    {
        int c = tid & 127, h = tid >> 7;
        const float4* er = (const float4*)(emb + (size_t)(c0 + c) * DD) + h * 16;
#pragma unroll
        for (int i = 0; i < 16; i++) {
            float4 v = er[i];
            int k = (h * 16 + i) * 4;
            ebT[(k + 0) * 128 + c] = v.x; ebT[(k + 1) * 128 + c] = v.y;
            ebT[(k + 2) * 128 + c] = v.z; ebT[(k + 3) * 128 + c] = v.w;
        }
    }
    __syncthreads();

    const int rg = tid >> 4;  // 0..15: code rows {rg*4+i, 64+rg*4+i}
    const int tc = tid & 15;  // 0..15: dims      {tc*4+j, 64+tc*4+j}

    float acc[8][8];
#pragma unroll
    for (int i = 0; i < 8; i++)
#pragma unroll
        for (int j = 0; j < 8; j++) acc[i][j] = 0.f;

#pragma unroll 4
    for (int k = 0; k < DD; k++) {
        float4 a0 = *(const float4*)(ebT + k * 128 + rg * 4);
        float4 a1 = *(const float4*)(ebT + k * 128 + 64 + rg * 4);
        float4 b0 = *(const float4*)(pwT + k * 128 + tc * 4);
        float4 b1 = *(const float4*)(pwT + k * 128 + 64 + tc * 4);
        float av[8] = {a0.x, a0.y, a0.z, a0.w, a1.x, a1.y, a1.z, a1.w};
        float bv[8] = {b0.x, b0.y, b0.z, b0.w, b1.x, b1.y, b1.z, b1.w};
#pragma unroll
        for (int i = 0; i < 8; i++)
#pragma unroll
            for (int j = 0; j < 8; j++) acc[i][j] += av[i] * bv[j];
    }

    // bias, store qc, accumulate cnorm
    float pbv[8];
#pragma unroll
    for (int j = 0; j < 8; j++)
        pbv[j] = pb[(j < 4) ? (tc * 4 + j) : (64 + tc * 4 + (j - 4))];

#pragma unroll
    for (int i = 0; i < 8; i++) {
        int code = (i < 4) ? (rg * 4 + i) : (64 + rg * 4 + (i - 4));
        float s = 0.f;
        float4 o0, o1;
        float v;
        v = acc[i][0] + pbv[0]; o0.x = v; s += v * v;
        v = acc[i][1] + pbv[1]; o0.y = v; s += v * v;
        v = acc[i][2] + pbv[2]; o0.z = v; s += v * v;
        v = acc[i][3] + pbv[3]; o0.w = v; s += v * v;
        v = acc[i][4] + pbv[4]; o1.x = v; s += v * v;
        v = acc[i][5] + pbv[5]; o1.y = v; s += v * v;
        v = acc[i][6] + pbv[6]; o1.z = v; s += v * v;
        v = acc[i][7] + pbv[7]; o1.w = v; s += v * v;
        float* qr = g_qc + (size_t)(c0 + code) * DD;
        *(float4*)(qr + tc * 4) = o0;
        *(float4*)(qr + 64 + tc * 4) = o1;
        atomicAdd(&cn_s[code], s);
    }
    __syncthreads();
    if (tid < 128) g_cnorm[c0 + tid] = cn_s[tid];
}

// ---------------------------------------------------------------------------
// Kernel 2: fused distance + argmin + gather + counts + commit, FFMA2 core.
// 128 blocks x 64 rows; K-loop in TN=256 tiles; 256 threads;
// micro-tile 8 rows (4 packed pairs) x 8 cols.
// dyn smem: zs[DD][TM] 32KB + cs[DD][TN] 128KB + znorm[64] + bestkey u64[64]
// ---------------------------------------------------------------------------
__global__ __launch_bounds__(256, 1) void k_argmin(const float* __restrict__ z,
                                                   float* __restrict__ out) {
    float* zs = smem_dyn;              // [d*TM + r]
    float* cs = smem_dyn + DD * TM;    // [d*TN + c]
    float* znorm_s = cs + DD * TN;     // [64]
    ull* bestkey = (ull*)(znorm_s + TM);

    const int tid = threadIdx.x;
    const int n0 = blockIdx.x * TM;
    const int rg = tid >> 5;  // 0..7  -> rows {rg*4+i, 32+rg*4+i}
    const int tc = tid & 31;  // 0..31 -> cols {tc*4+j, 128+tc*4+j}

    // load z tile transposed (d-major)
    {
        int r = tid & 63, dq = tid >> 6;
        const float4* zr = (const float4*)(z + (size_t)(n0 + r) * DD) + dq * 8;
#pragma unroll
        for (int i = 0; i < 8; i++) {
            float4 v = zr[i];
            int d = (dq * 8 + i) * 4;
            zs[(d + 0) * TM + r] = v.x; zs[(d + 1) * TM + r] = v.y;
            zs[(d + 2) * TM + r] = v.z; zs[(d + 3) * TM + r] = v.w;
        }
    }
    if (tid < TM) bestkey[tid] = ~0ULL;
    __syncthreads();

    if (tid < TM) {
        float s = 0.f;
#pragma unroll 16
        for (int d = 0; d < DD; d++) { float v = zs[d * TM + tid]; s += v * v; }
        znorm_s[tid] = s;
    }
    __syncthreads();

    float zn[8];
#pragma unroll
    for (int i = 0; i < 8; i++)
        zn[i] = znorm_s[(i < 4) ? (rg * 4 + i) : (32 + rg * 4 + (i - 4))];

    float bestv[8];
    int bestidx[8];
#pragma unroll
    for (int i = 0; i < 8; i++) { bestv[i] = 3.4e38f; bestidx[i] = 0; }

    const float* zpA = zs + rg * 4;
    const float* zpB = zs + 32 + rg * 4;
    const float* cp0 = cs + tc * 4;
    const float* cp1 = cs + 128 + tc * 4;

    for (int kt = 0; kt < KC; kt += TN) {
        // load code tile (d-major transpose via scalar STS)
        __syncthreads();
        {
            const float4* src = (const float4*)g_qc + (size_t)(kt + tid) * (DD / 4);
#pragma unroll
            for (int i = 0; i < 32; i++) {
                float4 v = src[i];
                int d = i * 4;
                cs[(d + 0) * TN + tid] = v.x; cs[(d + 1) * TN + tid] = v.y;
                cs[(d + 2) * TN + tid] = v.z; cs[(d + 3) * TN + tid] = v.w;
            }
        }
        __syncthreads();

        ull acc[4][8];
#pragma unroll
        for (int p = 0; p < 4; p++)
#pragma unroll
            for (int j = 0; j < 8; j++) acc[p][j] = 0ULL;

#pragma unroll 4
        for (int d = 0; d < DD; d++) {
            ulonglong2 aA = *(const ulonglong2*)(zpA + d * TM);  // pairs (r0,r1),(r2,r3)
            ulonglong2 aB = *(const ulonglong2*)(zpB + d * TM);
            float4 b0 = *(const float4*)(cp0 + d * TN);
            float4 b1 = *(const float4*)(cp1 + d * TN);
            ull bd[8];
            bd[0] = pack2(b0.x); bd[1] = pack2(b0.y); bd[2] = pack2(b0.z); bd[3] = pack2(b0.w);
            bd[4] = pack2(b1.x); bd[5] = pack2(b1.y); bd[6] = pack2(b1.z); bd[7] = pack2(b1.w);
            ull av[4] = {aA.x, aA.y, aB.x, aB.y};
#pragma unroll
            for (int p = 0; p < 4; p++)
#pragma unroll
                for (int j = 0; j < 8; j++) acc[p][j] = ffma2(av[p], bd[j], acc[p][j]);
        }

        // epilogue: d = (||z||^2+||c||^2) - 2*dot, track per-row best
#pragma unroll
        for (int j = 0; j < 8; j++) {
            int col = (j < 4) ? (tc * 4 + j) : (128 + tc * 4 + (j - 4));
            int code = kt + col;
            float cn = __ldg(&g_cnorm[code]);
#pragma unroll
            for (int p = 0; p < 4; p++) {
                float2 dot = unpack2(acc[p][j]);
                int i0 = (p < 2) ? (2 * p) : (4 + 2 * (p - 2));  // slot of even row
                float s0 = (zn[i0] + cn) - 2.0f * dot.x;
                float s1 = (zn[i0 + 1] + cn) - 2.0f * dot.y;
                if (s0 < bestv[i0]) { bestv[i0] = s0; bestidx[i0] = code; }
                if (s1 < bestv[i0 + 1]) { bestv[i0 + 1] = s1; bestidx[i0 + 1] = code; }
            }
        }
    }

    // merge per-thread bests into per-row (value||index) keys; atomicMin picks
    // smallest distance then smallest index (matches argmin semantics)
#pragma unroll
    for (int i = 0; i < 8; i++) {
        int row = (i < 4) ? (rg * 4 + i) : (32 + rg * 4 + (i - 4));
        unsigned ub = __float_as_uint(bestv[i]);
        ub = (ub & 0x80000000u) ? ~ub : (ub | 0x80000000u);
        ull key = ((ull)ub << 32) | (unsigned)bestidx[i];
        atomicMin(&bestkey[row], key);
    }
    __syncthreads();

    if (tid < TM) {
        unsigned idxk = (unsigned)(bestkey[tid] & 0xffffffffu);
        atomicAdd(&g_counts[idxk], 1.0f);
    }

    // gather z_q = z + (qc[idx]-z); accumulate commit partial
    float csum = 0.f;
    {
        int r = tid >> 2, part = tid & 3;
        unsigned idxk = (unsigned)(bestkey[r] & 0xffffffffu);
        const float4* qv = (const float4*)(g_qc + (size_t)idxk * DD) + part * 8;
        const float4* zv = (const float4*)(z + (size_t)(n0 + r) * DD) + part * 8;
        float4* ov = (float4*)(out + (size_t)(n0 + r) * DD) + part * 8;
#pragma unroll
        for (int i = 0; i < 8; i++) {
            float4 q = qv[i], zz = zv[i], o;
            float dx = q.x - zz.x, dy = q.y - zz.y, dz2 = q.z - zz.z, dw = q.w - zz.w;
            o.x = zz.x + dx; o.y = zz.y + dy; o.z = zz.z + dz2; o.w = zz.w + dw;
            ov[i] = o;
            csum += dx * dx; csum += dy * dy; csum += dz2 * dz2; csum += dw * dw;
        }
    }
#pragma unroll
    for (int o = 16; o; o >>= 1) csum += __shfl_xor_sync(0xffffffffu, csum, o);
    __shared__ float credu[8];
    if ((tid & 31) == 0) credu[tid >> 5] = csum;
    __syncthreads();
    if (tid == 0) {
        float t = 0.f;
#pragma unroll
        for (int i = 0; i < 8; i++) t += credu[i];
        atomicAdd(&g_commit, t);
    }
}

// ---------------------------------------------------------------------------
// Kernel 3: finalize scalars
// ---------------------------------------------------------------------------
__global__ __launch_bounds__(256) void k_final(const float* __restrict__ ema,
                                               float* __restrict__ out,
                                               int out_size) {
    __shared__ float r1[8], r2[8];
    int tid = threadIdx.x;
    const float omd = 1.0f - 0.99f;
    float s1 = 0.f, s2 = 0.f;
    for (int k = tid; k < KC; k += 256) {
        float em = g_counts[k] * (1.0f / NR);
        s1 += em * logf(em + 1e-10f);
        float nu = ema[k] * 0.99f + em * omd;
        s2 += nu * logf(nu + 1e-10f);
    }
#pragma unroll
    for (int o = 16; o; o >>= 1) {
        s1 += __shfl_xor_sync(0xffffffffu, s1, o);
        s2 += __shfl_xor_sync(0xffffffffu, s2, o);
    }
    if ((tid & 31) == 0) { r1[tid >> 5] = s1; r2[tid >> 5] = s2; }
    __syncthreads();
    if (tid == 0) {
        float S1 = 0.f, S2 = 0.f;
#pragma unroll
        for (int i = 0; i < 8; i++) { S1 += r1[i]; S2 += r2[i]; }
        out[out_size - 3] = 1.25f * g_commit * (1.0f / ((float)NR * (float)DD));
        out[out_size - 2] = expf(-S1);
        out[out_size - 1] = -S2;
    }
}

// ---------------------------------------------------------------------------
extern "C" void kernel_launch(void* const* d_in, const int* in_sizes, int n_in,
                              void* d_out, int out_size) {
    const float* z   = (const float*)d_in[0];
    const float* emb = (const float*)d_in[1];
    const float* pw  = (const float*)d_in[2];
    const float* pb  = (const float*)d_in[3];
    const float* ema = (const float*)d_in[4];
    float* out = (float*)d_out;

    const int smem_proj = (16384 + 16384 + 128) * 4;                 // 131584
    const int smem_arg  = (DD * TM + DD * TN + TM) * 4 + TM * 8;     // 164608
    cudaFuncSetAttribute(k_proj, cudaFuncAttributeMaxDynamicSharedMemorySize,
                         smem_proj);
    cudaFuncSetAttribute(k_argmin, cudaFuncAttributeMaxDynamicSharedMemorySize,
                         smem_arg);

    k_proj<<<KC / 128, 256, smem_proj>>>(emb, pw, pb);
    k_argmin<<<NR / TM, 256, smem_arg>>>(z, out);
    k_final<<<1, 256>>>(ema, out, out_size);
}